// round 2
// baseline (speedup 1.0000x reference)
#include <cuda_runtime.h>
#include <cuda_fp16.h>

#define N_CLI 100000
#define N_AGG 1000
#define NE    1600000
#define D     128
#define NLAY  3

#define BM 128
#define BN 128
#define BK 32
#define FUSED_SMEM 67584   // max(128*36 + 32*128, 128*132) * 4 bytes

// ---------------- scratch (device globals; no allocation allowed) ----------------
__device__ float  g_xc0[N_CLI * D];
__device__ float  g_xc1[N_CLI * D];
__device__ float  g_xa0[N_AGG * D];
__device__ float  g_xa1[N_AGG * D];
__device__ __half g_Y16[N_AGG * D];
__device__ __half g_xc16a[N_CLI * D];   // fp16 copy of layer-l input clients (l=0)
__device__ __half g_xc16b[N_CLI * D];   // fp16 copy of layer-0 output clients
__device__ float  g_mean_a[N_AGG * D];
__device__ int    g_csr_c2a[NE];
__device__ int    g_csr_a2c[NE];
__device__ int    g_off_c2a[N_AGG + 1];
__device__ int    g_off_a2c[N_CLI + 1];
__device__ int    g_cur_c2a[N_AGG];
__device__ int    g_cur_a2c[N_CLI];
__device__ int    g_cnt_c2a[N_AGG];
__device__ int    g_cnt_a2c[N_CLI];
__device__ float  g_invc_a[N_AGG];
__device__ float  g_invc_c[N_CLI];

// ---------------- CSR construction ----------------
__global__ void zero_int_kernel(int* p, int n) {
    int i = blockIdx.x * blockDim.x + threadIdx.x;
    if (i < n) p[i] = 0;
}

__global__ void hist_c2a_kernel(const int* __restrict__ dst, int* __restrict__ cnt) {
    __shared__ int h[N_AGG];
    for (int i = threadIdx.x; i < N_AGG; i += blockDim.x) h[i] = 0;
    __syncthreads();
    for (int e = blockIdx.x * blockDim.x + threadIdx.x; e < NE; e += gridDim.x * blockDim.x)
        atomicAdd(&h[dst[e]], 1);
    __syncthreads();
    for (int i = threadIdx.x; i < N_AGG; i += blockDim.x)
        if (h[i]) atomicAdd(&cnt[i], h[i]);
}

__global__ void hist_a2c_kernel(const int* __restrict__ dst, int* __restrict__ cnt) {
    int e = blockIdx.x * blockDim.x + threadIdx.x;
    if (e < NE) atomicAdd(&cnt[dst[e]], 1);
}

__global__ void scan_init_kernel(const int* __restrict__ cnt, int* __restrict__ off,
                                 int* __restrict__ cur, float* __restrict__ invc, int n) {
    __shared__ int wsum[32];
    __shared__ int carry;
    int tid = threadIdx.x, lane = tid & 31, wid = tid >> 5;
    if (tid == 0) carry = 0;
    __syncthreads();
    for (int base = 0; base < n; base += 1024) {
        int i = base + tid;
        int v = (i < n) ? cnt[i] : 0;
        int x = v;
        #pragma unroll
        for (int o = 1; o < 32; o <<= 1) {
            int t = __shfl_up_sync(0xffffffffu, x, o);
            if (lane >= o) x += t;
        }
        if (lane == 31) wsum[wid] = x;
        __syncthreads();
        if (wid == 0) {
            int s = wsum[lane];
            #pragma unroll
            for (int o = 1; o < 32; o <<= 1) {
                int t = __shfl_up_sync(0xffffffffu, s, o);
                if (lane >= o) s += t;
            }
            wsum[lane] = s;
        }
        __syncthreads();
        int excl = x - v + (wid ? wsum[wid - 1] : 0) + carry;
        if (i < n) {
            off[i] = excl;
            cur[i] = excl;
            invc[i] = 1.0f / fmaxf((float)v, 1.0f);
        }
        __syncthreads();
        if (tid == 0) carry += wsum[31];
        __syncthreads();
    }
    if (threadIdx.x == 0) off[n] = carry;
}

__global__ void scatter_kernel(const int* __restrict__ src, const int* __restrict__ dst,
                               int* __restrict__ cur, int* __restrict__ csr) {
    int e = blockIdx.x * blockDim.x + threadIdx.x;
    if (e < NE) {
        int p = atomicAdd(&cur[dst[e]], 1);
        csr[p] = src[e];
    }
}

// ---------------- fp32 -> fp16 feature conversion ----------------
__global__ void f2h_kernel(const float* __restrict__ x, __half* __restrict__ y, int n4) {
    int i = blockIdx.x * blockDim.x + threadIdx.x;
    if (i < n4) {
        float4 v = ((const float4*)x)[i];
        __half2 h0 = __floats2half2_rn(v.x, v.y);
        __half2 h1 = __floats2half2_rn(v.z, v.w);
        ((__half2*)y)[i * 2]     = h0;
        ((__half2*)y)[i * 2 + 1] = h1;
    }
}

// ---------------- tiny GEMM: Y16 = xa @ Wl (fp16 output) ----------------
__global__ void gemm_small_h_kernel(const float* __restrict__ A, const float* __restrict__ W,
                                    __half* __restrict__ C) {
    __shared__ float row[D];
    int r = blockIdx.x, j = threadIdx.x;
    row[j] = A[r * D + j];
    __syncthreads();
    float acc = 0.f;
    #pragma unroll 8
    for (int k = 0; k < D; k++) acc += row[k] * W[k * D + j];
    C[r * D + j] = __float2half(acc);
}

// xa_new = leaky(mean @ Wl + xa @ Wr + b)
__global__ void agg_update_kernel(const float* __restrict__ mean, const float* __restrict__ xa,
                                  const float* __restrict__ Wl, const float* __restrict__ Wr,
                                  const float* __restrict__ b, float* __restrict__ out) {
    __shared__ float rm[D], rx[D];
    int r = blockIdx.x, j = threadIdx.x;
    rm[j] = mean[r * D + j];
    rx[j] = xa[r * D + j];
    __syncthreads();
    float acc = b[j];
    #pragma unroll 4
    for (int k = 0; k < D; k++) acc += rm[k] * Wl[k * D + j] + rx[k] * Wr[k * D + j];
    out[r * D + j] = (acc >= 0.f) ? acc : 0.1f * acc;
}

// ---------------- c2a aggregation from fp16 client features ----------------
__global__ void agg_c2a_h_kernel(const __half* __restrict__ xc16, const int* __restrict__ csr,
                                 const int* __restrict__ off, const float* __restrict__ invc,
                                 float* __restrict__ mean) {
    int a = blockIdx.x, j = threadIdx.x;
    int s = off[a], e = off[a + 1];
    float acc0 = 0.f, acc1 = 0.f, acc2 = 0.f, acc3 = 0.f;
    int i = s;
    for (; i + 4 <= e; i += 4) {
        int i0 = csr[i], i1 = csr[i + 1], i2 = csr[i + 2], i3 = csr[i + 3];
        acc0 += __half2float(xc16[i0 * D + j]);
        acc1 += __half2float(xc16[i1 * D + j]);
        acc2 += __half2float(xc16[i2 * D + j]);
        acc3 += __half2float(xc16[i3 * D + j]);
    }
    for (; i < e; i++) acc0 += __half2float(xc16[csr[i] * D + j]);
    mean[a * D + j] = (acc0 + acc1 + acc2 + acc3) * invc[a];
}

// ---------------- fused: Z = A @ Wr + b, then per-client gather(Y16)+leaky ----------------
// LAST: emit only scalar out = leaky(..) . W_lin + b_lin
// W16:  additionally write fp16 copy of xc_out
template<bool LAST, bool W16>
__global__ void __launch_bounds__(256)
fused_client_kernel(const float* __restrict__ A, const float* __restrict__ W,
                    const float* __restrict__ bias, const __half* __restrict__ Y16,
                    const int* __restrict__ csr, const int* __restrict__ off,
                    const float* __restrict__ invc,
                    float* __restrict__ xc_out, __half* __restrict__ xc16,
                    const float* __restrict__ Wlin, const float* __restrict__ blin,
                    float* __restrict__ outv, int M) {
    extern __shared__ char smraw[];
    float* sAs  = (float*)smraw;                 // [128][36] mainloop
    float* sWs  = sAs + BM * (BK + 4);           // [32][128] mainloop
    float* tile = (float*)smraw;                 // [128][132] epilogue (aliases)

    int tid = threadIdx.x;
    int tn = tid & 15, tm = tid >> 4;
    int r0 = blockIdx.x * BM;
    float acc[8][8];
    #pragma unroll
    for (int i = 0; i < 8; i++)
        #pragma unroll
        for (int j = 0; j < 8; j++) acc[i][j] = 0.f;

    int rowA0 = tm * 4;
    int colB0 = tn * 4;

    for (int kc = 0; kc < D; kc += BK) {
        {
            int r = tid >> 3;
            int kq = tid & 7;
            #pragma unroll
            for (int p = 0; p < 4; p++) {
                int row = r0 + r + p * 32;
                int rc = (row < M) ? row : (M - 1);
                float4 v = *(const float4*)(&A[rc * D + kc + kq * 4]);
                *(float4*)(&sAs[(r + p * 32) * (BK + 4) + kq * 4]) = v;
            }
        }
        {
            int n4 = tid & 31, kk = tid >> 5;
            #pragma unroll
            for (int p = 0; p < 4; p++) {
                int k = kk + p * 8;
                *(float4*)(&sWs[k * BN + n4 * 4]) = *(const float4*)(&W[(kc + k) * D + n4 * 4]);
            }
        }
        __syncthreads();
        #pragma unroll
        for (int k = 0; k < BK; k++) {
            float a[8], b[8];
            #pragma unroll
            for (int i = 0; i < 4; i++) {
                a[i]     = sAs[(rowA0 + i) * (BK + 4) + k];
                a[i + 4] = sAs[(rowA0 + 64 + i) * (BK + 4) + k];
            }
            float4 b0 = *(const float4*)(&sWs[k * BN + colB0]);
            float4 b1 = *(const float4*)(&sWs[k * BN + colB0 + 64]);
            b[0] = b0.x; b[1] = b0.y; b[2] = b0.z; b[3] = b0.w;
            b[4] = b1.x; b[5] = b1.y; b[6] = b1.z; b[7] = b1.w;
            #pragma unroll
            for (int i = 0; i < 8; i++)
                #pragma unroll
                for (int j = 0; j < 8; j++) acc[i][j] += a[i] * b[j];
        }
        __syncthreads();
    }

    // Write GEMM result (+bias) into the smem tile (pitch 132 floats keeps 16B alignment)
    float4 bj0 = *(const float4*)(&bias[colB0]);
    float4 bj1 = *(const float4*)(&bias[colB0 + 64]);
    #pragma unroll
    for (int i = 0; i < 8; i++) {
        int row = rowA0 + ((i < 4) ? i : (64 + i - 4));
        float4 o0, o1;
        o0.x = acc[i][0] + bj0.x; o0.y = acc[i][1] + bj0.y;
        o0.z = acc[i][2] + bj0.z; o0.w = acc[i][3] + bj0.w;
        o1.x = acc[i][4] + bj1.x; o1.y = acc[i][5] + bj1.y;
        o1.z = acc[i][6] + bj1.z; o1.w = acc[i][7] + bj1.w;
        *(float4*)(&tile[row * 132 + colB0]) = o0;
        *(float4*)(&tile[row * 132 + colB0 + 64]) = o1;
    }
    __syncthreads();

    // Gather epilogue: warp w handles client rows w*16 .. w*16+15
    int warp = tid >> 5, lane = tid & 31;
    const float2* Y2 = (const float2*)Y16;
    float4 wl4 = make_float4(0.f, 0.f, 0.f, 0.f);
    if (LAST) wl4 = ((const float4*)Wlin)[lane];

    for (int rr = 0; rr < 16; rr++) {
        int row = warp * 16 + rr;
        int c = r0 + row;
        if (c >= M) break;
        int s = off[c], e = off[c + 1];
        float4 macc = make_float4(0.f, 0.f, 0.f, 0.f);
        for (int base = s; base < e; base += 32) {
            int nv = min(32, e - base);
            int idx = (lane < nv) ? csr[base + lane] : 0;
            for (int t = 0; t < nv; t++) {
                int a = __shfl_sync(0xffffffffu, idx, t);
                float2 raw = Y2[a * 32 + lane];
                __half2 h0 = *(__half2*)&raw.x;
                __half2 h1 = *(__half2*)&raw.y;
                float2 f0 = __half22float2(h0);
                float2 f1 = __half22float2(h1);
                macc.x += f0.x; macc.y += f0.y; macc.z += f1.x; macc.w += f1.y;
            }
        }
        float ic = invc[c];
        float4 z = *(float4*)(&tile[row * 132 + lane * 4]);
        float4 v;
        v.x = z.x + macc.x * ic;
        v.y = z.y + macc.y * ic;
        v.z = z.z + macc.z * ic;
        v.w = z.w + macc.w * ic;
        v.x = (v.x >= 0.f) ? v.x : 0.1f * v.x;
        v.y = (v.y >= 0.f) ? v.y : 0.1f * v.y;
        v.z = (v.z >= 0.f) ? v.z : 0.1f * v.z;
        v.w = (v.w >= 0.f) ? v.w : 0.1f * v.w;
        if (LAST) {
            float p = v.x * wl4.x + v.y * wl4.y + v.z * wl4.z + v.w * wl4.w;
            #pragma unroll
            for (int o = 16; o; o >>= 1) p += __shfl_xor_sync(0xffffffffu, p, o);
            if (lane == 0) outv[c] = p + blin[0];
        } else {
            ((float4*)xc_out)[c * 32 + lane] = v;
            if (W16) {
                __half2 h0 = __floats2half2_rn(v.x, v.y);
                __half2 h1 = __floats2half2_rn(v.z, v.w);
                float2 pk;
                *(__half2*)&pk.x = h0;
                *(__half2*)&pk.y = h1;
                ((float2*)xc16)[c * 32 + lane] = pk;
            }
        }
    }
}

// ---------------- launch ----------------
extern "C" void kernel_launch(void* const* d_in, const int* in_sizes, int n_in,
                              void* d_out, int out_size) {
    (void)in_sizes; (void)n_in; (void)out_size;
    const float* x_clients = (const float*)d_in[0];
    const float* x_agg     = (const float*)d_in[1];
    const int*   c2a_src   = (const int*)d_in[2];
    const int*   c2a_dst   = (const int*)d_in[3];
    const int*   a2c_src   = (const int*)d_in[4];
    const int*   a2c_dst   = (const int*)d_in[5];
    const float* Wl_c2a    = (const float*)d_in[6];
    const float* Wr_c2a    = (const float*)d_in[7];
    const float* b_c2a     = (const float*)d_in[8];
    const float* Wl_a2c    = (const float*)d_in[9];
    const float* Wr_a2c    = (const float*)d_in[10];
    const float* b_a2c     = (const float*)d_in[11];
    const float* W_lin     = (const float*)d_in[12];
    const float* b_lin     = (const float*)d_in[13];
    float* out = (float*)d_out;

    void *p_xc0, *p_xc1, *p_xa0, *p_xa1, *p_Y16, *p_xc16a, *p_xc16b, *p_mean;
    void *p_csr_c2a, *p_csr_a2c, *p_off_c2a, *p_off_a2c;
    void *p_cur_c2a, *p_cur_a2c, *p_cnt_c2a, *p_cnt_a2c, *p_invc_a, *p_invc_c;
    cudaGetSymbolAddress(&p_xc0, g_xc0);
    cudaGetSymbolAddress(&p_xc1, g_xc1);
    cudaGetSymbolAddress(&p_xa0, g_xa0);
    cudaGetSymbolAddress(&p_xa1, g_xa1);
    cudaGetSymbolAddress(&p_Y16, g_Y16);
    cudaGetSymbolAddress(&p_xc16a, g_xc16a);
    cudaGetSymbolAddress(&p_xc16b, g_xc16b);
    cudaGetSymbolAddress(&p_mean, g_mean_a);
    cudaGetSymbolAddress(&p_csr_c2a, g_csr_c2a);
    cudaGetSymbolAddress(&p_csr_a2c, g_csr_a2c);
    cudaGetSymbolAddress(&p_off_c2a, g_off_c2a);
    cudaGetSymbolAddress(&p_off_a2c, g_off_a2c);
    cudaGetSymbolAddress(&p_cur_c2a, g_cur_c2a);
    cudaGetSymbolAddress(&p_cur_a2c, g_cur_a2c);
    cudaGetSymbolAddress(&p_cnt_c2a, g_cnt_c2a);
    cudaGetSymbolAddress(&p_cnt_a2c, g_cnt_a2c);
    cudaGetSymbolAddress(&p_invc_a, g_invc_a);
    cudaGetSymbolAddress(&p_invc_c, g_invc_c);

    cudaFuncSetAttribute(fused_client_kernel<false, true>,
                         cudaFuncAttributeMaxDynamicSharedMemorySize, FUSED_SMEM);
    cudaFuncSetAttribute(fused_client_kernel<false, false>,
                         cudaFuncAttributeMaxDynamicSharedMemorySize, FUSED_SMEM);
    cudaFuncSetAttribute(fused_client_kernel<true, false>,
                         cudaFuncAttributeMaxDynamicSharedMemorySize, FUSED_SMEM);

    float* xcb[2] = {(float*)p_xc0, (float*)p_xc1};
    float* xab[2] = {(float*)p_xa0, (float*)p_xa1};

    // ---- CSR build ----
    zero_int_kernel<<<(N_AGG + 255) / 256, 256>>>((int*)p_cnt_c2a, N_AGG);
    zero_int_kernel<<<(N_CLI + 255) / 256, 256>>>((int*)p_cnt_a2c, N_CLI);
    hist_c2a_kernel<<<296, 256>>>(c2a_dst, (int*)p_cnt_c2a);
    hist_a2c_kernel<<<(NE + 255) / 256, 256>>>(a2c_dst, (int*)p_cnt_a2c);
    scan_init_kernel<<<1, 1024>>>((const int*)p_cnt_c2a, (int*)p_off_c2a,
                                  (int*)p_cur_c2a, (float*)p_invc_a, N_AGG);
    scan_init_kernel<<<1, 1024>>>((const int*)p_cnt_a2c, (int*)p_off_a2c,
                                  (int*)p_cur_a2c, (float*)p_invc_c, N_CLI);
    scatter_kernel<<<(NE + 255) / 256, 256>>>(c2a_src, c2a_dst, (int*)p_cur_c2a, (int*)p_csr_c2a);
    scatter_kernel<<<(NE + 255) / 256, 256>>>(a2c_src, a2c_dst, (int*)p_cur_a2c, (int*)p_csr_a2c);

    // fp16 copy of initial client features (for layer-0 c2a gather)
    f2h_kernel<<<(N_CLI * 32 + 255) / 256, 256>>>(x_clients, (__half*)p_xc16a, N_CLI * 32);

    const float* xc_in = x_clients;
    const float* xa_in = x_agg;
    const __half* xc16_in = (const __half*)p_xc16a;
    int grid_fused = (N_CLI + BM - 1) / BM;

    for (int l = 0; l < NLAY; l++) {
        const float* WlA = Wl_a2c + l * D * D;
        const float* WrA = Wr_a2c + l * D * D;
        const float* bA  = b_a2c + l * D;
        const float* WlC = Wl_c2a + l * D * D;
        const float* WrC = Wr_c2a + l * D * D;
        const float* bC  = b_c2a + l * D;
        float* xc_out = xcb[l & 1];
        float* xa_out = xab[l & 1];

        // c2a path first (uses pre-update xc); dead in last layer
        if (l < NLAY - 1) {
            agg_c2a_h_kernel<<<N_AGG, 128>>>(xc16_in, (const int*)p_csr_c2a,
                                             (const int*)p_off_c2a, (const float*)p_invc_a,
                                             (float*)p_mean);
            agg_update_kernel<<<N_AGG, 128>>>((const float*)p_mean, xa_in, WlC, WrC, bC, xa_out);
        }

        // a2c path: Y16 = xa @ Wl (fp16), then fused Z-GEMM + gather + leaky
        gemm_small_h_kernel<<<N_AGG, 128>>>(xa_in, WlA, (__half*)p_Y16);
        if (l == 0) {
            fused_client_kernel<false, true><<<grid_fused, 256, FUSED_SMEM>>>(
                xc_in, WrA, bA, (const __half*)p_Y16, (const int*)p_csr_a2c,
                (const int*)p_off_a2c, (const float*)p_invc_c,
                xc_out, (__half*)p_xc16b, W_lin, b_lin, out, N_CLI);
            xc16_in = (const __half*)p_xc16b;
        } else if (l < NLAY - 1) {
            fused_client_kernel<false, false><<<grid_fused, 256, FUSED_SMEM>>>(
                xc_in, WrA, bA, (const __half*)p_Y16, (const int*)p_csr_a2c,
                (const int*)p_off_a2c, (const float*)p_invc_c,
                xc_out, (__half*)0, W_lin, b_lin, out, N_CLI);
        } else {
            fused_client_kernel<true, false><<<grid_fused, 256, FUSED_SMEM>>>(
                xc_in, WrA, bA, (const __half*)p_Y16, (const int*)p_csr_a2c,
                (const int*)p_off_a2c, (const float*)p_invc_c,
                xc_out, (__half*)0, W_lin, b_lin, out, N_CLI);
        }

        if (l < NLAY - 1) xa_in = xab[l & 1];
        xc_in = xc_out;
    }
}

// round 3
// speedup vs baseline: 1.7285x; 1.7285x over previous
#include <cuda_runtime.h>
#include <cuda_fp16.h>
#include <mma.h>
using namespace nvcuda;

#define N_CLI 100000
#define N_AGG 1000
#define NE    1600000
#define D     128
#define NLAY  3

#define GEMM_SMEM (2 * 128 * 136 * 2)   // 69632 B

// ---------------- scratch (device globals; no allocation allowed) ----------------
__device__ float  g_xa0[N_AGG * D];
__device__ float  g_xa1[N_AGG * D];
__device__ __half g_Y16[N_AGG * D];
__device__ __half g_xc16a[N_CLI * D];
__device__ __half g_xc16b[N_CLI * D];
__device__ __half g_W16[D * D];
__device__ float  g_Z[(N_CLI + 128) * D];   // padded for full-tile stores
__device__ float  g_mean_a[N_AGG * D];
__device__ int    g_csr_c2a[NE];
__device__ int    g_csr_a2c[NE];
__device__ int    g_off_c2a[N_AGG + 1];
__device__ int    g_off_a2c[N_CLI + 1];
__device__ int    g_cur_c2a[N_AGG];
__device__ int    g_cur_a2c[N_CLI];
__device__ int    g_cnt_c2a[N_AGG];
__device__ int    g_cnt_a2c[N_CLI];
__device__ int    g_part[128];
__device__ float  g_invc_a[N_AGG];
__device__ float  g_invc_c[N_CLI];

// ---------------- CSR construction ----------------
__global__ void zero_int_kernel(int* p, int n) {
    int i = blockIdx.x * blockDim.x + threadIdx.x;
    if (i < n) p[i] = 0;
}

__global__ void hist_c2a_kernel(const int* __restrict__ dst, int* __restrict__ cnt) {
    __shared__ int h[N_AGG];
    for (int i = threadIdx.x; i < N_AGG; i += blockDim.x) h[i] = 0;
    __syncthreads();
    for (int e = blockIdx.x * blockDim.x + threadIdx.x; e < NE; e += gridDim.x * blockDim.x)
        atomicAdd(&h[dst[e]], 1);
    __syncthreads();
    for (int i = threadIdx.x; i < N_AGG; i += blockDim.x)
        if (h[i]) atomicAdd(&cnt[i], h[i]);
}

__global__ void hist_a2c_kernel(const int* __restrict__ dst, int* __restrict__ cnt) {
    int e = blockIdx.x * blockDim.x + threadIdx.x;
    if (e < NE) atomicAdd(&cnt[dst[e]], 1);
}

// single-block scan (used for the small N_AGG side)
__global__ void scan_init_kernel(const int* __restrict__ cnt, int* __restrict__ off,
                                 int* __restrict__ cur, float* __restrict__ invc, int n) {
    __shared__ int wsum[32];
    __shared__ int carry;
    int tid = threadIdx.x, lane = tid & 31, wid = tid >> 5;
    if (tid == 0) carry = 0;
    __syncthreads();
    for (int base = 0; base < n; base += 1024) {
        int i = base + tid;
        int v = (i < n) ? cnt[i] : 0;
        int x = v;
        #pragma unroll
        for (int o = 1; o < 32; o <<= 1) {
            int t = __shfl_up_sync(0xffffffffu, x, o);
            if (lane >= o) x += t;
        }
        if (lane == 31) wsum[wid] = x;
        __syncthreads();
        if (wid == 0) {
            int s = wsum[lane];
            #pragma unroll
            for (int o = 1; o < 32; o <<= 1) {
                int t = __shfl_up_sync(0xffffffffu, s, o);
                if (lane >= o) s += t;
            }
            wsum[lane] = s;
        }
        __syncthreads();
        int excl = x - v + (wid ? wsum[wid - 1] : 0) + carry;
        if (i < n) {
            off[i] = excl;
            cur[i] = excl;
            invc[i] = 1.0f / fmaxf((float)v, 1.0f);
        }
        __syncthreads();
        if (tid == 0) carry += wsum[31];
        __syncthreads();
    }
    if (threadIdx.x == 0) off[n] = carry;
}

// ---- multi-block scan for the big (N_CLI) side ----
__global__ void scan_blocks_kernel(const int* __restrict__ cnt, int* __restrict__ off,
                                   int* __restrict__ part, int n) {
    __shared__ int wsum[32];
    int tid = threadIdx.x, lane = tid & 31, wid = tid >> 5;
    int i = blockIdx.x * 1024 + tid;
    int v = (i < n) ? cnt[i] : 0;
    int x = v;
    #pragma unroll
    for (int o = 1; o < 32; o <<= 1) {
        int t = __shfl_up_sync(0xffffffffu, x, o);
        if (lane >= o) x += t;
    }
    if (lane == 31) wsum[wid] = x;
    __syncthreads();
    if (wid == 0) {
        int s = wsum[lane];
        #pragma unroll
        for (int o = 1; o < 32; o <<= 1) {
            int t = __shfl_up_sync(0xffffffffu, s, o);
            if (lane >= o) s += t;
        }
        wsum[lane] = s;
    }
    __syncthreads();
    int excl = x - v + (wid ? wsum[wid - 1] : 0);
    if (i < n) off[i] = excl;
    if (tid == 1023) part[blockIdx.x] = excl + v;
}

__global__ void scan_part_kernel(int* part, int nb) {
    if (threadIdx.x == 0) {
        int acc = 0;
        for (int b = 0; b < nb; b++) {
            int v = part[b];
            part[b] = acc;
            acc += v;
        }
        part[nb] = acc;
    }
}

__global__ void scan_add_kernel(const int* __restrict__ cnt, int* __restrict__ off,
                                const int* __restrict__ part, int* __restrict__ cur,
                                float* __restrict__ invc, int n, int nb) {
    int i = blockIdx.x * blockDim.x + threadIdx.x;
    if (i < n) {
        int o = off[i] + part[i >> 10];
        off[i] = o;
        cur[i] = o;
        invc[i] = 1.0f / fmaxf((float)cnt[i], 1.0f);
    }
    if (i == 0) off[n] = part[nb];
}

__global__ void scatter_kernel(const int* __restrict__ src, const int* __restrict__ dst,
                               int* __restrict__ cur, int* __restrict__ csr) {
    int e = blockIdx.x * blockDim.x + threadIdx.x;
    if (e < NE) {
        int p = atomicAdd(&cur[dst[e]], 1);
        csr[p] = src[e];
    }
}

// ---------------- fp32 -> fp16 conversion ----------------
__global__ void f2h_kernel(const float* __restrict__ x, __half* __restrict__ y, int n4) {
    int i = blockIdx.x * blockDim.x + threadIdx.x;
    if (i < n4) {
        float4 v = ((const float4*)x)[i];
        __half2 h0 = __floats2half2_rn(v.x, v.y);
        __half2 h1 = __floats2half2_rn(v.z, v.w);
        float2 pk;
        *(__half2*)&pk.x = h0;
        *(__half2*)&pk.y = h1;
        ((float2*)y)[i] = pk;
    }
}

// ---------------- tiny GEMM: Y16 = xa @ Wl ----------------
__global__ void gemm_small_h_kernel(const float* __restrict__ A, const float* __restrict__ W,
                                    __half* __restrict__ C) {
    __shared__ float row[D];
    int r = blockIdx.x, j = threadIdx.x;
    row[j] = A[r * D + j];
    __syncthreads();
    float acc = 0.f;
    #pragma unroll 8
    for (int k = 0; k < D; k++) acc += row[k] * W[k * D + j];
    C[r * D + j] = __float2half(acc);
}

// xa_new = leaky(mean @ Wl + xa @ Wr + b)
__global__ void agg_update_kernel(const float* __restrict__ mean, const float* __restrict__ xa,
                                  const float* __restrict__ Wl, const float* __restrict__ Wr,
                                  const float* __restrict__ b, float* __restrict__ out) {
    __shared__ float rm[D], rx[D];
    int r = blockIdx.x, j = threadIdx.x;
    rm[j] = mean[r * D + j];
    rx[j] = xa[r * D + j];
    __syncthreads();
    float acc = b[j];
    #pragma unroll 4
    for (int k = 0; k < D; k++) acc += rm[k] * Wl[k * D + j] + rx[k] * Wr[k * D + j];
    out[r * D + j] = (acc >= 0.f) ? acc : 0.1f * acc;
}

// ---------------- c2a aggregation from fp16 client features ----------------
__global__ void agg_c2a_h_kernel(const __half* __restrict__ xc16, const int* __restrict__ csr,
                                 const int* __restrict__ off, const float* __restrict__ invc,
                                 float* __restrict__ mean) {
    int a = blockIdx.x, j = threadIdx.x;
    int s = off[a], e = off[a + 1];
    float acc0 = 0.f, acc1 = 0.f, acc2 = 0.f, acc3 = 0.f;
    int i = s;
    for (; i + 4 <= e; i += 4) {
        int i0 = csr[i], i1 = csr[i + 1], i2 = csr[i + 2], i3 = csr[i + 3];
        acc0 += __half2float(xc16[i0 * D + j]);
        acc1 += __half2float(xc16[i1 * D + j]);
        acc2 += __half2float(xc16[i2 * D + j]);
        acc3 += __half2float(xc16[i3 * D + j]);
    }
    for (; i < e; i++) acc0 += __half2float(xc16[csr[i] * D + j]);
    mean[a * D + j] = (acc0 + acc1 + acc2 + acc3) * invc[a];
}

// ---------------- tensor-core GEMM: Z = A16(Mx128) @ W16(128x128), fp32 out ----------------
__global__ void __launch_bounds__(256)
gemm_h_kernel(const __half* __restrict__ A, const __half* __restrict__ W,
              float* __restrict__ Z, int M) {
    extern __shared__ __half sm[];
    __half* sA = sm;                 // [128][136]
    __half* sW = sm + 128 * 136;     // [128][136]
    int tid = threadIdx.x;
    int r0 = blockIdx.x * 128;

    // load tiles: 128 rows x 128 halfs each; 8 halfs per float4
    for (int i = tid; i < 128 * 16; i += 256) {
        int row = i >> 4, c8 = (i & 15) * 8;
        int rc = min(r0 + row, M - 1);
        float4 v = *(const float4*)(A + (size_t)rc * D + c8);
        *(float4*)(&sA[row * 136 + c8]) = v;
    }
    for (int i = tid; i < 128 * 16; i += 256) {
        int row = i >> 4, c8 = (i & 15) * 8;
        float4 v = *(const float4*)(W + row * D + c8);
        *(float4*)(&sW[row * 136 + c8]) = v;
    }
    __syncthreads();

    int warp = tid >> 5;
    int wm = warp >> 1;   // 0..3 -> 32 rows each
    int wn = warp & 1;    // 0..1 -> 64 cols each

    wmma::fragment<wmma::accumulator, 16, 16, 16, float> acc[2][4];
    #pragma unroll
    for (int i = 0; i < 2; i++)
        #pragma unroll
        for (int j = 0; j < 4; j++) wmma::fill_fragment(acc[i][j], 0.f);

    #pragma unroll
    for (int k = 0; k < 128; k += 16) {
        wmma::fragment<wmma::matrix_a, 16, 16, 16, __half, wmma::row_major> af[2];
        wmma::fragment<wmma::matrix_b, 16, 16, 16, __half, wmma::row_major> bf[4];
        #pragma unroll
        for (int i = 0; i < 2; i++)
            wmma::load_matrix_sync(af[i], &sA[(wm * 32 + i * 16) * 136 + k], 136);
        #pragma unroll
        for (int j = 0; j < 4; j++)
            wmma::load_matrix_sync(bf[j], &sW[k * 136 + wn * 64 + j * 16], 136);
        #pragma unroll
        for (int i = 0; i < 2; i++)
            #pragma unroll
            for (int j = 0; j < 4; j++)
                wmma::mma_sync(acc[i][j], af[i], bf[j], acc[i][j]);
    }

    #pragma unroll
    for (int i = 0; i < 2; i++)
        #pragma unroll
        for (int j = 0; j < 4; j++)
            wmma::store_matrix_sync(&Z[(size_t)(r0 + wm * 32 + i * 16) * D + wn * 64 + j * 16],
                                    acc[i][j], D, wmma::mem_row_major);
}

// ---------------- client update: xc16_new = leaky(Z + b + gathersum(Y16)/cnt) ----------------
template<bool LAST>
__global__ void client_update_h_kernel(const float* __restrict__ Z, const float* __restrict__ bias,
                                       const __half* __restrict__ Y16,
                                       const int* __restrict__ csr, const int* __restrict__ off,
                                       const float* __restrict__ invc,
                                       __half* __restrict__ xc16,
                                       const float* __restrict__ Wlin,
                                       const float* __restrict__ blin,
                                       float* __restrict__ outv) {
    __shared__ float sb[D];
    if (threadIdx.x < D) sb[threadIdx.x] = bias[threadIdx.x];
    __syncthreads();
    int warp = (blockIdx.x * blockDim.x + threadIdx.x) >> 5;
    int lane = threadIdx.x & 31;
    if (warp >= N_CLI) return;
    int s = off[warp], e = off[warp + 1];
    const float2* Y2 = (const float2*)Y16;
    float4 acc = make_float4(0.f, 0.f, 0.f, 0.f);
    for (int base = s; base < e; base += 32) {
        int nv = min(32, e - base);
        int idx = (lane < nv) ? csr[base + lane] : 0;
        for (int t = 0; t < nv; t++) {
            int a = __shfl_sync(0xffffffffu, idx, t);
            float2 raw = Y2[a * 32 + lane];
            __half2 h0 = *(__half2*)&raw.x;
            __half2 h1 = *(__half2*)&raw.y;
            float2 f0 = __half22float2(h0);
            float2 f1 = __half22float2(h1);
            acc.x += f0.x; acc.y += f0.y; acc.z += f1.x; acc.w += f1.y;
        }
    }
    float ic = invc[warp];
    float4 z = ((const float4*)Z)[warp * 32 + lane];
    float4 b4 = *(const float4*)(&sb[lane * 4]);
    float4 v;
    v.x = z.x + b4.x + acc.x * ic;
    v.y = z.y + b4.y + acc.y * ic;
    v.z = z.z + b4.z + acc.z * ic;
    v.w = z.w + b4.w + acc.w * ic;
    v.x = (v.x >= 0.f) ? v.x : 0.1f * v.x;
    v.y = (v.y >= 0.f) ? v.y : 0.1f * v.y;
    v.z = (v.z >= 0.f) ? v.z : 0.1f * v.z;
    v.w = (v.w >= 0.f) ? v.w : 0.1f * v.w;
    if (LAST) {
        float4 w4 = ((const float4*)Wlin)[lane];
        float p = v.x * w4.x + v.y * w4.y + v.z * w4.z + v.w * w4.w;
        #pragma unroll
        for (int o = 16; o; o >>= 1) p += __shfl_xor_sync(0xffffffffu, p, o);
        if (lane == 0) outv[warp] = p + blin[0];
    } else {
        __half2 h0 = __floats2half2_rn(v.x, v.y);
        __half2 h1 = __floats2half2_rn(v.z, v.w);
        float2 pk;
        *(__half2*)&pk.x = h0;
        *(__half2*)&pk.y = h1;
        ((float2*)xc16)[warp * 32 + lane] = pk;
    }
}

// ---------------- launch ----------------
extern "C" void kernel_launch(void* const* d_in, const int* in_sizes, int n_in,
                              void* d_out, int out_size) {
    (void)in_sizes; (void)n_in; (void)out_size;
    const float* x_clients = (const float*)d_in[0];
    const float* x_agg     = (const float*)d_in[1];
    const int*   c2a_src   = (const int*)d_in[2];
    const int*   c2a_dst   = (const int*)d_in[3];
    const int*   a2c_src   = (const int*)d_in[4];
    const int*   a2c_dst   = (const int*)d_in[5];
    const float* Wl_c2a    = (const float*)d_in[6];
    const float* Wr_c2a    = (const float*)d_in[7];
    const float* b_c2a     = (const float*)d_in[8];
    const float* Wl_a2c    = (const float*)d_in[9];
    const float* Wr_a2c    = (const float*)d_in[10];
    const float* b_a2c     = (const float*)d_in[11];
    const float* W_lin     = (const float*)d_in[12];
    const float* b_lin     = (const float*)d_in[13];
    float* out = (float*)d_out;

    void *p_xa0, *p_xa1, *p_Y16, *p_xc16a, *p_xc16b, *p_W16, *p_Z, *p_mean;
    void *p_csr_c2a, *p_csr_a2c, *p_off_c2a, *p_off_a2c;
    void *p_cur_c2a, *p_cur_a2c, *p_cnt_c2a, *p_cnt_a2c, *p_part, *p_invc_a, *p_invc_c;
    cudaGetSymbolAddress(&p_xa0, g_xa0);
    cudaGetSymbolAddress(&p_xa1, g_xa1);
    cudaGetSymbolAddress(&p_Y16, g_Y16);
    cudaGetSymbolAddress(&p_xc16a, g_xc16a);
    cudaGetSymbolAddress(&p_xc16b, g_xc16b);
    cudaGetSymbolAddress(&p_W16, g_W16);
    cudaGetSymbolAddress(&p_Z, g_Z);
    cudaGetSymbolAddress(&p_mean, g_mean_a);
    cudaGetSymbolAddress(&p_csr_c2a, g_csr_c2a);
    cudaGetSymbolAddress(&p_csr_a2c, g_csr_a2c);
    cudaGetSymbolAddress(&p_off_c2a, g_off_c2a);
    cudaGetSymbolAddress(&p_off_a2c, g_off_a2c);
    cudaGetSymbolAddress(&p_cur_c2a, g_cur_c2a);
    cudaGetSymbolAddress(&p_cur_a2c, g_cur_a2c);
    cudaGetSymbolAddress(&p_cnt_c2a, g_cnt_c2a);
    cudaGetSymbolAddress(&p_cnt_a2c, g_cnt_a2c);
    cudaGetSymbolAddress(&p_part, g_part);
    cudaGetSymbolAddress(&p_invc_a, g_invc_a);
    cudaGetSymbolAddress(&p_invc_c, g_invc_c);

    cudaFuncSetAttribute(gemm_h_kernel, cudaFuncAttributeMaxDynamicSharedMemorySize, GEMM_SMEM);

    __half* xc16b_[2] = {(__half*)p_xc16a, (__half*)p_xc16b};
    float* xab[2] = {(float*)p_xa0, (float*)p_xa1};

    // ---- CSR build ----
    zero_int_kernel<<<(N_AGG + 255) / 256, 256>>>((int*)p_cnt_c2a, N_AGG);
    zero_int_kernel<<<(N_CLI + 255) / 256, 256>>>((int*)p_cnt_a2c, N_CLI);
    hist_c2a_kernel<<<296, 256>>>(c2a_dst, (int*)p_cnt_c2a);
    hist_a2c_kernel<<<(NE + 255) / 256, 256>>>(a2c_dst, (int*)p_cnt_a2c);
    scan_init_kernel<<<1, 1024>>>((const int*)p_cnt_c2a, (int*)p_off_c2a,
                                  (int*)p_cur_c2a, (float*)p_invc_a, N_AGG);
    int nb = (N_CLI + 1023) / 1024;
    scan_blocks_kernel<<<nb, 1024>>>((const int*)p_cnt_a2c, (int*)p_off_a2c, (int*)p_part, N_CLI);
    scan_part_kernel<<<1, 32>>>((int*)p_part, nb);
    scan_add_kernel<<<(N_CLI + 255) / 256, 256>>>((const int*)p_cnt_a2c, (int*)p_off_a2c,
                                                  (const int*)p_part, (int*)p_cur_a2c,
                                                  (float*)p_invc_c, N_CLI, nb);
    scatter_kernel<<<(NE + 255) / 256, 256>>>(c2a_src, c2a_dst, (int*)p_cur_c2a, (int*)p_csr_c2a);
    scatter_kernel<<<(NE + 255) / 256, 256>>>(a2c_src, a2c_dst, (int*)p_cur_a2c, (int*)p_csr_a2c);

    // fp16 copy of initial client features
    f2h_kernel<<<(N_CLI * 32 + 255) / 256, 256>>>(x_clients, (__half*)p_xc16a, N_CLI * 32);

    const float* xa_in = x_agg;
    const __half* xc16_in = (const __half*)p_xc16a;
    int grid_gemm = (N_CLI + 127) / 128;
    int grid_cu = (N_CLI * 32 + 255) / 256;

    for (int l = 0; l < NLAY; l++) {
        const float* WlA = Wl_a2c + l * D * D;
        const float* WrA = Wr_a2c + l * D * D;
        const float* bA  = b_a2c + l * D;
        const float* WlC = Wl_c2a + l * D * D;
        const float* WrC = Wr_c2a + l * D * D;
        const float* bC  = b_c2a + l * D;
        __half* xc16_out = xc16b_[(l + 1) & 1];

        // c2a path (uses pre-update xc16); dead in last layer
        if (l < NLAY - 1) {
            agg_c2a_h_kernel<<<N_AGG, 128>>>(xc16_in, (const int*)p_csr_c2a,
                                             (const int*)p_off_c2a, (const float*)p_invc_a,
                                             (float*)p_mean);
            agg_update_kernel<<<N_AGG, 128>>>((const float*)p_mean, xa_in, WlC, WrC, bC,
                                              xab[l & 1]);
        }

        // a2c path
        gemm_small_h_kernel<<<N_AGG, 128>>>(xa_in, WlA, (__half*)p_Y16);
        f2h_kernel<<<(D * D / 4 + 255) / 256, 256>>>(WrA, (__half*)p_W16, D * D / 4);
        gemm_h_kernel<<<grid_gemm, 256, GEMM_SMEM>>>(xc16_in, (const __half*)p_W16,
                                                     (float*)p_Z, N_CLI);
        if (l < NLAY - 1) {
            client_update_h_kernel<false><<<grid_cu, 256>>>(
                (const float*)p_Z, bA, (const __half*)p_Y16, (const int*)p_csr_a2c,
                (const int*)p_off_a2c, (const float*)p_invc_c, xc16_out,
                W_lin, b_lin, out);
        } else {
            client_update_h_kernel<true><<<grid_cu, 256>>>(
                (const float*)p_Z, bA, (const __half*)p_Y16, (const int*)p_csr_a2c,
                (const int*)p_off_a2c, (const float*)p_invc_c, xc16_out,
                W_lin, b_lin, out);
        }

        if (l < NLAY - 1) xa_in = xab[l & 1];
        xc16_in = xc16_out;
    }
}